// round 4
// baseline (speedup 1.0000x reference)
#include <cuda_runtime.h>
#include <math.h>

// Problem constants
#define B_    2
#define S_    4096
#define HID_  1024
#define NH_   16
#define HD_   64
#define W_    128
#define NB_   (S_ / W_)          // 32 query blocks per sequence
#define M_    (B_ * S_)          // 8192 rows

// Scratch (device globals — no runtime allocation allowed).
// __align__(16): __device__ float arrays only guarantee 4B alignment, but the
// sgemm/attention kernels access these with 128-bit loads/stores.
__device__ __align__(16) float g_q  [M_ * HID_];
__device__ __align__(16) float g_k  [M_ * HID_];
__device__ __align__(16) float g_v  [M_ * HID_];
__device__ __align__(16) float g_ctx[M_ * HID_];

// ---------------------------------------------------------------------------
// SGEMM (NT): C[M,N] = A[M,K] @ Bw[N,K]^T + bias[N]
// Both A and Bw are K-contiguous row-major. 128x128 tile, BK=8, 256 threads,
// 8x8 microtile per thread with 4+4 row/col split for LDS.128 fragments.
// ---------------------------------------------------------------------------
__global__ void __launch_bounds__(256)
sgemm_nt_kernel(const float* __restrict__ A, const float* __restrict__ Bw,
                const float* __restrict__ bias, float* __restrict__ C,
                int M, int N, int K)
{
    __shared__ float As[8][128];
    __shared__ float Bs[8][128];

    const int tid = threadIdx.x;
    const int bm  = blockIdx.y * 128;
    const int bn  = blockIdx.x * 128;

    // Global-load mapping: one float4 from A and one from Bw per K-step.
    const int lr = tid >> 1;          // 0..127 (row within tile)
    const int lc = (tid & 1) * 4;     // 0 or 4 (k offset)
    const float* Ap = A  + (size_t)(bm + lr) * K + lc;
    const float* Bp = Bw + (size_t)(bn + lr) * K + lc;

    const int tx = tid & 15;          // 0..15 (col group)
    const int ty = tid >> 4;          // 0..15 (row group)

    float acc[8][8];
#pragma unroll
    for (int i = 0; i < 8; i++)
#pragma unroll
        for (int j = 0; j < 8; j++) acc[i][j] = 0.0f;

    for (int k0 = 0; k0 < K; k0 += 8) {
        // Issue global loads early; latency overlaps previous tile's math.
        float4 av = *(const float4*)(Ap + k0);
        float4 bv = *(const float4*)(Bp + k0);

        __syncthreads();   // previous iteration's smem reads complete
        As[lc + 0][lr] = av.x; As[lc + 1][lr] = av.y;
        As[lc + 2][lr] = av.z; As[lc + 3][lr] = av.w;
        Bs[lc + 0][lr] = bv.x; Bs[lc + 1][lr] = bv.y;
        Bs[lc + 2][lr] = bv.z; Bs[lc + 3][lr] = bv.w;
        __syncthreads();

#pragma unroll
        for (int kk = 0; kk < 8; kk++) {
            float4 a0 = *(const float4*)&As[kk][ty * 4];
            float4 a1 = *(const float4*)&As[kk][64 + ty * 4];
            float4 b0 = *(const float4*)&Bs[kk][tx * 4];
            float4 b1 = *(const float4*)&Bs[kk][64 + tx * 4];
            float a[8] = {a0.x, a0.y, a0.z, a0.w, a1.x, a1.y, a1.z, a1.w};
            float b[8] = {b0.x, b0.y, b0.z, b0.w, b1.x, b1.y, b1.z, b1.w};
#pragma unroll
            for (int i = 0; i < 8; i++)
#pragma unroll
                for (int j = 0; j < 8; j++)
                    acc[i][j] = fmaf(a[i], b[j], acc[i][j]);
        }
    }

    // Epilogue: bias + float4 stores
#pragma unroll
    for (int i = 0; i < 8; i++) {
        const int row = bm + ((i < 4) ? (ty * 4 + i) : (64 + ty * 4 + (i - 4)));
#pragma unroll
        for (int jh = 0; jh < 2; jh++) {
            const int col = bn + jh * 64 + tx * 4;
            float4 out;
            out.x = acc[i][jh * 4 + 0] + bias[col + 0];
            out.y = acc[i][jh * 4 + 1] + bias[col + 1];
            out.z = acc[i][jh * 4 + 2] + bias[col + 2];
            out.w = acc[i][jh * 4 + 3] + bias[col + 3];
            *(float4*)&C[(size_t)row * N + col] = out;
        }
    }
}

// ---------------------------------------------------------------------------
// RoPE (llama half-split), in-place on q and k laid out [B*S, NH*HD].
// One thread per (b,s,h,pair). Matches reference fp32 math:
//   inv_freq = 10000^(-(2i)/64), ang = pos*inv_freq
//   out[i]    = x[i]*cos - x[i+32]*sin
//   out[i+32] = x[i+32]*cos + x[i]*sin
// ---------------------------------------------------------------------------
__global__ void __launch_bounds__(256)
rope_kernel(float* __restrict__ q, float* __restrict__ k)
{
    const int idx = blockIdx.x * blockDim.x + threadIdx.x;   // B*S*NH*32 total
    const int i   = idx & 31;
    const int h   = (idx >> 5) & 15;
    const int bs  = idx >> 9;               // 0 .. B*S-1
    const int pos = bs & (S_ - 1);
    const int base = bs * HID_ + h * HD_ + i;

    const float ex   = (float)(2 * i) * (1.0f / 64.0f);
    const float invf = powf(10000.0f, -ex);
    const float ang  = (float)pos * invf;
    float sn, cs;
    sincosf(ang, &sn, &cs);

    float x1 = q[base], x2 = q[base + 32];
    q[base]      = x1 * cs - x2 * sn;
    q[base + 32] = x2 * cs + x1 * sn;

    float y1 = k[base], y2 = k[base + 32];
    k[base]      = y1 * cs - y2 * sn;
    k[base + 32] = y2 * cs + y1 * sn;
}

// ---------------------------------------------------------------------------
// Sliding-window block attention.
// Grid: (NB_, NH_, B_). 128 threads, thread r owns query row r of the block.
// Keys = [previous block | current block] (256 keys), band mask r<=j<=r+128,
// block 0 masks out the (zero-pad) previous chunk entirely.
// smem: scores [128][257] (odd stride: bank = (r+j)%32, conflict-free row
//       access in the softmax loop; vector staging through sc is therefore
//       SCALARIZED — r*257 floats is not 16B-aligned for odd r)
//       kv     [128][64]   (K then V chunks, broadcast reads, float4-aligned)
// ---------------------------------------------------------------------------
#define SROW 257
#define ATT_SMEM ((128 * SROW + 128 * 64) * (int)sizeof(float))

__global__ void __launch_bounds__(128)
swattn_kernel(const float* __restrict__ q, const float* __restrict__ k,
              const float* __restrict__ v, float* __restrict__ ctx)
{
    extern __shared__ float sm[];
    float* sc = sm;                 // [128][SROW]
    float* kv = sm + 128 * SROW;    // [128][64]

    const int n = blockIdx.x, h = blockIdx.y, b = blockIdx.z;
    const int t   = threadIdx.x;
    const int r   = t;              // query row within block
    const int c16 = t & 15;         // cooperative-load column group
    const int r8  = t >> 4;         // cooperative-load row group
    const int rowbase = b * S_ + n * W_;   // first query row (global)

    // ---- Stage Q (coalesced global read, scalar smem write) ----
    for (int rr = r8; rr < W_; rr += 8) {
        float4 val = *(const float4*)&q[(size_t)(rowbase + rr) * HID_ + h * HD_ + c16 * 4];
        float* dst = &sc[rr * SROW + c16 * 4];
        dst[0] = val.x; dst[1] = val.y; dst[2] = val.z; dst[3] = val.w;
    }
    __syncthreads();
    float qr[64];
#pragma unroll
    for (int d = 0; d < 64; d++) qr[d] = sc[r * SROW + d];
    // From here each thread writes/reads only its OWN sc row until the output
    // staging step, so no extra syncs are needed around sc accesses.

    const int c0 = (n == 0) ? 1 : 0;
    if (n == 0) {
        for (int j = 0; j < 128; j++) sc[r * SROW + j] = -1e30f;
    }

    // ---- Scores: S = Q K^T * scale, masked ----
    for (int chunk = c0; chunk < 2; chunk++) {
        const int kb = rowbase + (chunk - 1) * W_;
        __syncthreads();   // prior kv readers done
        for (int rr = r8; rr < W_; rr += 8)
            *(float4*)&kv[rr * 64 + c16 * 4] =
                *(const float4*)&k[(size_t)(kb + rr) * HID_ + h * HD_ + c16 * 4];
        __syncthreads();

        for (int j = 0; j < 128; j++) {
            float a0 = 0.f, a1 = 0.f, a2 = 0.f, a3 = 0.f;
#pragma unroll
            for (int d = 0; d < 64; d += 4) {
                float4 k4 = *(const float4*)&kv[j * 64 + d];
                a0 = fmaf(qr[d + 0], k4.x, a0);
                a1 = fmaf(qr[d + 1], k4.y, a1);
                a2 = fmaf(qr[d + 2], k4.z, a2);
                a3 = fmaf(qr[d + 3], k4.w, a3);
            }
            float sv = ((a0 + a1) + (a2 + a3)) * 0.125f;   // 1/sqrt(64)
            const int jl = chunk * 128 + j;
            const bool valid = (jl >= r) && (jl <= r + 128);
            sc[r * SROW + jl] = valid ? sv : -1e30f;
        }
    }

    // ---- Softmax over own row (unnormalized; fold 1/sum into epilogue) ----
    float mx = -1e30f;
    for (int j = 0; j < 256; j++) mx = fmaxf(mx, sc[r * SROW + j]);
    float sum = 0.f;
    for (int j = 0; j < 256; j++) {
        float p = __expf(sc[r * SROW + j] - mx);
        sc[r * SROW + j] = p;
        sum += p;
    }
    const float invsum = 1.0f / sum;

    // ---- O = P V ----
    float o[64];
#pragma unroll
    for (int d = 0; d < 64; d++) o[d] = 0.f;

    for (int chunk = c0; chunk < 2; chunk++) {
        const int kb = rowbase + (chunk - 1) * W_;
        __syncthreads();   // score-phase kv readers done
        for (int rr = r8; rr < W_; rr += 8)
            *(float4*)&kv[rr * 64 + c16 * 4] =
                *(const float4*)&v[(size_t)(kb + rr) * HID_ + h * HD_ + c16 * 4];
        __syncthreads();

        for (int j = 0; j < 128; j++) {
            float p = sc[r * SROW + chunk * 128 + j];
#pragma unroll
            for (int d = 0; d < 64; d += 4) {
                float4 v4 = *(const float4*)&kv[j * 64 + d];
                o[d + 0] = fmaf(p, v4.x, o[d + 0]);
                o[d + 1] = fmaf(p, v4.y, o[d + 1]);
                o[d + 2] = fmaf(p, v4.z, o[d + 2]);
                o[d + 3] = fmaf(p, v4.w, o[d + 3]);
            }
        }
    }

    // ---- Stage O through smem (scalar smem, coalesced global store) ----
    __syncthreads();
#pragma unroll
    for (int d = 0; d < 64; d++) sc[r * SROW + d] = o[d] * invsum;
    __syncthreads();
    for (int rr = r8; rr < W_; rr += 8) {
        const float* src = &sc[rr * SROW + c16 * 4];
        float4 val;
        val.x = src[0]; val.y = src[1]; val.z = src[2]; val.w = src[3];
        *(float4*)&ctx[(size_t)(rowbase + rr) * HID_ + h * HD_ + c16 * 4] = val;
    }
}

// ---------------------------------------------------------------------------
// Launch: QKV GEMMs -> RoPE -> attention -> output GEMM
// ---------------------------------------------------------------------------
extern "C" void kernel_launch(void* const* d_in, const int* in_sizes, int n_in,
                              void* d_out, int out_size)
{
    const float* hidden = (const float*)d_in[0];
    const float* Wq = (const float*)d_in[1];
    const float* bq = (const float*)d_in[2];
    const float* Wk = (const float*)d_in[3];
    const float* bk = (const float*)d_in[4];
    const float* Wv = (const float*)d_in[5];
    const float* bv = (const float*)d_in[6];
    const float* Wo = (const float*)d_in[7];
    const float* bo = (const float*)d_in[8];
    float* out = (float*)d_out;

    float *qp, *kp, *vp, *cp;
    cudaGetSymbolAddress((void**)&qp, g_q);
    cudaGetSymbolAddress((void**)&kp, g_k);
    cudaGetSymbolAddress((void**)&vp, g_v);
    cudaGetSymbolAddress((void**)&cp, g_ctx);

    // Not a stream op; idempotent, called every time (no static guards).
    cudaFuncSetAttribute(swattn_kernel,
                         cudaFuncAttributeMaxDynamicSharedMemorySize, ATT_SMEM);

    dim3 gemm_grid(HID_ / 128, M_ / 128);   // (8, 64)

    sgemm_nt_kernel<<<gemm_grid, 256>>>(hidden, Wq, bq, qp, M_, HID_, HID_);
    sgemm_nt_kernel<<<gemm_grid, 256>>>(hidden, Wk, bk, kp, M_, HID_, HID_);
    sgemm_nt_kernel<<<gemm_grid, 256>>>(hidden, Wv, bv, vp, M_, HID_, HID_);

    rope_kernel<<<(M_ * NH_ * 32) / 256, 256>>>(qp, kp);

    dim3 att_grid(NB_, NH_, B_);            // (32, 16, 2)
    swattn_kernel<<<att_grid, 128, ATT_SMEM>>>(qp, kp, vp, cp);

    sgemm_nt_kernel<<<gemm_grid, 256>>>(cp, Wo, bo, out, M_, HID_, HID_);
}

// round 8
// speedup vs baseline: 1.5554x; 1.5554x over previous
#include <cuda_runtime.h>
#include <cuda_bf16.h>
#include <math.h>
#include <stdint.h>

// Problem constants
#define B_    2
#define S_    4096
#define HID_  1024
#define NH_   16
#define HD_   64
#define W_    128
#define NB_   (S_ / W_)
#define M_    (B_ * S_)          // 8192

// bf16-split GEMM: single GEMM with K tripled (hi/lo 3-term correction)
#define KPK   3072               // 3 * 1024
#define BK    32                 // bf16 k per mainloop iter
#define NITER (KPK / BK)         // 96
#define ASTR  80                 // smem row stride bytes (64B data + 16B pad)
#define STGB  (2 * 128 * ASTR)   // A + B per stage = 20480
#define NSTG  3
#define GEMM_SMEM (NSTG * STGB)  // 61440

// ---------------- scratch (device globals; no runtime alloc) ----------------
__device__ __align__(16)  float g_q  [M_ * HID_];
__device__ __align__(16)  float g_k  [M_ * HID_];
__device__ __align__(16)  float g_v  [M_ * HID_];
__device__ __align__(16)  float g_ctx[M_ * HID_];
__device__ __align__(128) __nv_bfloat16 g_A2[(size_t)M_ * KPK];        // 50MB
__device__ __align__(128) __nv_bfloat16 g_B2[4][(size_t)HID_ * KPK];   // 4x6MB

// ---------------- PTX helpers (plain sm_80+ ISA only) ----------------
__device__ __forceinline__ uint32_t smem_u32(const void* p) {
    uint32_t a;
    asm("{ .reg .u64 t; cvta.to.shared.u64 t, %1; cvt.u32.u64 %0, t; }"
        : "=r"(a) : "l"(p));
    return a;
}
__device__ __forceinline__ void cp16(uint32_t dst, const void* src) {
    asm volatile("cp.async.cg.shared.global [%0], [%1], 16;"
                 :: "r"(dst), "l"(src) : "memory");
}
#define CP_COMMIT() asm volatile("cp.async.commit_group;" ::: "memory")
#define CP_WAIT2()  asm volatile("cp.async.wait_group 2;" ::: "memory")
__device__ __forceinline__ void ldmx4(uint32_t* r, uint32_t addr) {
    asm volatile("ldmatrix.sync.aligned.m8n8.x4.shared.b16 {%0,%1,%2,%3}, [%4];"
                 : "=r"(r[0]), "=r"(r[1]), "=r"(r[2]), "=r"(r[3]) : "r"(addr));
}
__device__ __forceinline__ void mma16816(float* d, const uint32_t* a,
                                         const uint32_t* b) {
    asm volatile(
        "mma.sync.aligned.m16n8k16.row.col.f32.bf16.bf16.f32 "
        "{%0,%1,%2,%3}, {%4,%5,%6,%7}, {%8,%9}, {%0,%1,%2,%3};"
        : "+f"(d[0]), "+f"(d[1]), "+f"(d[2]), "+f"(d[3])
        : "r"(a[0]), "r"(a[1]), "r"(a[2]), "r"(a[3]), "r"(b[0]), "r"(b[1]));
}

// ---------------------------------------------------------------------------
// pack_split3: fp32 [R,1024] -> bf16 [R,3072].
// mode 0 (A operand): segments [hi | lo | hi]
// mode 1 (B operand): segments [hi | hi | lo]
// A'·B'^T = Ah·Bh + Al·Bh + Ah·Bl  (3-term bf16 split of fp32 product)
// ---------------------------------------------------------------------------
__global__ void __launch_bounds__(256)
pack_split3_kernel(const float* __restrict__ src, __nv_bfloat16* __restrict__ dst,
                   int mode)
{
    const int idx = blockIdx.x * 256 + threadIdx.x;   // one per 4 elements
    const int r   = idx >> 8;
    const int c4  = (idx & 255) * 4;

    const float4 x = *(const float4*)(src + (size_t)r * HID_ + c4);
    const float xs[4] = {x.x, x.y, x.z, x.w};
    uint32_t hw[2], lw[2];
#pragma unroll
    for (int j = 0; j < 2; j++) {
        __nv_bfloat16 h0 = __float2bfloat16(xs[2*j]);
        __nv_bfloat16 h1 = __float2bfloat16(xs[2*j+1]);
        __nv_bfloat16 l0 = __float2bfloat16(xs[2*j]   - __bfloat162float(h0));
        __nv_bfloat16 l1 = __float2bfloat16(xs[2*j+1] - __bfloat162float(h1));
        hw[j] = (uint32_t)__bfloat16_as_ushort(h0) |
                ((uint32_t)__bfloat16_as_ushort(h1) << 16);
        lw[j] = (uint32_t)__bfloat16_as_ushort(l0) |
                ((uint32_t)__bfloat16_as_ushort(l1) << 16);
    }
    const size_t base = (size_t)r * KPK + c4;
    uint2 hv = make_uint2(hw[0], hw[1]);
    uint2 lv = make_uint2(lw[0], lw[1]);
    *(uint2*)(dst + base)        = hv;
    *(uint2*)(dst + base + 1024) = (mode == 0) ? lv : hv;
    *(uint2*)(dst + base + 2048) = (mode == 0) ? hv : lv;
}

// ---------------------------------------------------------------------------
// bf16 mma.sync GEMM (NT): C[M,1024] = A2[M,3072] @ B2[1024,3072]^T + bias.
// CTA 128x128, 256 thr (8 warps, 4x2), warp tile 32x64, BK=32, 3-stage
// cp.async pipeline. Smem rows padded to 80B -> conflict-free ldmatrix.
// ---------------------------------------------------------------------------
__global__ void __launch_bounds__(256, 2)
gemm_bf16_kernel(const __nv_bfloat16* __restrict__ A2,
                 const __nv_bfloat16* __restrict__ B2,
                 const float* __restrict__ bias, float* __restrict__ C)
{
    extern __shared__ __align__(128) unsigned char sm_[];
    const uint32_t sb = smem_u32(sm_);

    const int bn = blockIdx.x * 128, bm = blockIdx.y * 128;
    const int tid = threadIdx.x, lane = tid & 31, w = tid >> 5;
    const int wm = w >> 1, wn = w & 1;

    // cp.async mapping: thread -> (row, 2 chunks) for A and B
    const int ld_row = tid >> 1;
    const int ld_ch  = (tid & 1) * 2;               // chunk 0-1 or 2-3
    const __nv_bfloat16* Ag = A2 + (size_t)(bm + ld_row) * KPK + ld_ch * 8;
    const __nv_bfloat16* Bg = B2 + (size_t)(bn + ld_row) * KPK + ld_ch * 8;
    const uint32_t As_w = sb + ld_row * ASTR + ld_ch * 16;
    const uint32_t Bs_w = As_w + 128 * ASTR;

    // ldmatrix per-thread invariant offsets
    const int a_lane_row = (lane < 16) ? lane : (lane - 16);
    const uint32_t a_off = (uint32_t)(a_lane_row * ASTR + ((lane < 16) ? 0 : 16)
                                      + wm * 32 * ASTR);
    const int quad  = lane >> 3;
    const int b_row = ((quad >> 1) << 3) + (lane & 7);
    const uint32_t b_off = (uint32_t)(128 * ASTR + b_row * ASTR + (quad & 1) * 16
                                      + wn * 64 * ASTR);

    float acc[2][8][4];
#pragma unroll
    for (int i = 0; i < 2; i++)
#pragma unroll
        for (int j = 0; j < 8; j++)
#pragma unroll
            for (int q = 0; q < 4; q++) acc[i][j][q] = 0.0f;

    // prologue: stages 0,1
#pragma unroll
    for (int s = 0; s < 2; s++) {
        const uint32_t so = s * STGB;
        cp16(As_w + so,      Ag + s * BK);
        cp16(As_w + so + 16, Ag + s * BK + 8);
        cp16(Bs_w + so,      Bg + s * BK);
        cp16(Bs_w + so + 16, Bg + s * BK + 8);
        CP_COMMIT();
    }

    for (int i = 0; i < NITER; i++) {
        // issue stage i+2 (one commit per iter keeps group accounting fixed)
        if (i + 2 < NITER) {
            const uint32_t so = ((i + 2) % NSTG) * STGB;
            cp16(As_w + so,      Ag + (i + 2) * BK);
            cp16(As_w + so + 16, Ag + (i + 2) * BK + 8);
            cp16(Bs_w + so,      Bg + (i + 2) * BK);
            cp16(Bs_w + so + 16, Bg + (i + 2) * BK + 8);
        }
        CP_COMMIT();

        CP_WAIT2();            // stage i complete
        __syncthreads();

        const uint32_t so = (i % NSTG) * STGB;
#pragma unroll
        for (int kk = 0; kk < 2; kk++) {
            uint32_t af0[4], af1[4], bfr[4][4];
            ldmx4(af0, sb + so + a_off + kk * 32);
            ldmx4(af1, sb + so + a_off + 16 * ASTR + kk * 32);
#pragma unroll
            for (int nt2 = 0; nt2 < 4; nt2++)
                ldmx4(bfr[nt2], sb + so + b_off + nt2 * 16 * ASTR + kk * 32);
#pragma unroll
            for (int nt = 0; nt < 8; nt++) {
                mma16816(acc[0][nt], af0, &bfr[nt >> 1][(nt & 1) * 2]);
                mma16816(acc[1][nt], af1, &bfr[nt >> 1][(nt & 1) * 2]);
            }
        }
        __syncthreads();       // all reads done before stage reuse
    }

    // Epilogue: c0,c1 -> (row g, cols 2t,2t+1); c2,c3 -> row g+8
    const int g  = lane >> 2;
    const int tq = lane & 3;
#pragma unroll
    for (int mt = 0; mt < 2; mt++) {
        const int r0 = bm + wm * 32 + mt * 16 + g;
#pragma unroll
        for (int nt = 0; nt < 8; nt++) {
            const int col = bn + wn * 64 + nt * 8 + tq * 2;
            const float2 b2v = *(const float2*)&bias[col];
            float2 o0, o1;
            o0.x = acc[mt][nt][0] + b2v.x;  o0.y = acc[mt][nt][1] + b2v.y;
            o1.x = acc[mt][nt][2] + b2v.x;  o1.y = acc[mt][nt][3] + b2v.y;
            *(float2*)&C[(size_t)r0 * HID_ + col]       = o0;
            *(float2*)&C[(size_t)(r0 + 8) * HID_ + col] = o1;
        }
    }
}

// ---------------------------------------------------------------------------
// RoPE (unchanged, proven)
// ---------------------------------------------------------------------------
__global__ void __launch_bounds__(256)
rope_kernel(float* __restrict__ q, float* __restrict__ k)
{
    const int idx = blockIdx.x * blockDim.x + threadIdx.x;
    const int i   = idx & 31;
    const int h   = (idx >> 5) & 15;
    const int bs  = idx >> 9;
    const int pos = bs & (S_ - 1);
    const int base = bs * HID_ + h * HD_ + i;

    const float ex   = (float)(2 * i) * (1.0f / 64.0f);
    const float invf = powf(10000.0f, -ex);
    const float ang  = (float)pos * invf;
    float sn, cs;
    sincosf(ang, &sn, &cs);

    float x1 = q[base], x2 = q[base + 32];
    q[base]      = x1 * cs - x2 * sn;
    q[base + 32] = x2 * cs + x1 * sn;

    float y1 = k[base], y2 = k[base + 32];
    k[base]      = y1 * cs - y2 * sn;
    k[base + 32] = y2 * cs + y1 * sn;
}

// ---------------------------------------------------------------------------
// Sliding-window block attention (unchanged, proven)
// ---------------------------------------------------------------------------
#define SROW 257
#define ATT_SMEM ((128 * SROW + 128 * 64) * (int)sizeof(float))

__global__ void __launch_bounds__(128)
swattn_kernel(const float* __restrict__ q, const float* __restrict__ k,
              const float* __restrict__ v, float* __restrict__ ctx)
{
    extern __shared__ float sm[];
    float* sc = sm;
    float* kv = sm + 128 * SROW;

    const int n = blockIdx.x, h = blockIdx.y, b = blockIdx.z;
    const int t   = threadIdx.x;
    const int r   = t;
    const int c16 = t & 15;
    const int r8  = t >> 4;
    const int rowbase = b * S_ + n * W_;

    for (int rr = r8; rr < W_; rr += 8) {
        float4 val = *(const float4*)&q[(size_t)(rowbase + rr) * HID_ + h * HD_ + c16 * 4];
        float* dst = &sc[rr * SROW + c16 * 4];
        dst[0] = val.x; dst[1] = val.y; dst[2] = val.z; dst[3] = val.w;
    }
    __syncthreads();
    float qr[64];
#pragma unroll
    for (int d = 0; d < 64; d++) qr[d] = sc[r * SROW + d];

    const int c0 = (n == 0) ? 1 : 0;
    if (n == 0) {
        for (int j = 0; j < 128; j++) sc[r * SROW + j] = -1e30f;
    }

    for (int chunk = c0; chunk < 2; chunk++) {
        const int kb = rowbase + (chunk - 1) * W_;
        __syncthreads();
        for (int rr = r8; rr < W_; rr += 8)
            *(float4*)&kv[rr * 64 + c16 * 4] =
                *(const float4*)&k[(size_t)(kb + rr) * HID_ + h * HD_ + c16 * 4];
        __syncthreads();

        for (int j = 0; j < 128; j++) {
            float a0 = 0.f, a1 = 0.f, a2 = 0.f, a3 = 0.f;
#pragma unroll
            for (int d = 0; d < 64; d += 4) {
                float4 k4 = *(const float4*)&kv[j * 64 + d];
                a0 = fmaf(qr[d + 0], k4.x, a0);
                a1 = fmaf(qr[d + 1], k4.y, a1);
                a2 = fmaf(qr[d + 2], k4.z, a2);
                a3 = fmaf(qr[d + 3], k4.w, a3);
            }
            float sv = ((a0 + a1) + (a2 + a3)) * 0.125f;
            const int jl = chunk * 128 + j;
            const bool valid = (jl >= r) && (jl <= r + 128);
            sc[r * SROW + jl] = valid ? sv : -1e30f;
        }
    }

    float mx = -1e30f;
    for (int j = 0; j < 256; j++) mx = fmaxf(mx, sc[r * SROW + j]);
    float sum = 0.f;
    for (int j = 0; j < 256; j++) {
        float p = __expf(sc[r * SROW + j] - mx);
        sc[r * SROW + j] = p;
        sum += p;
    }
    const float invsum = 1.0f / sum;

    float o[64];
#pragma unroll
    for (int d = 0; d < 64; d++) o[d] = 0.f;

    for (int chunk = c0; chunk < 2; chunk++) {
        const int kb = rowbase + (chunk - 1) * W_;
        __syncthreads();
        for (int rr = r8; rr < W_; rr += 8)
            *(float4*)&kv[rr * 64 + c16 * 4] =
                *(const float4*)&v[(size_t)(kb + rr) * HID_ + h * HD_ + c16 * 4];
        __syncthreads();

        for (int j = 0; j < 128; j++) {
            float p = sc[r * SROW + chunk * 128 + j];
#pragma unroll
            for (int d = 0; d < 64; d += 4) {
                float4 v4 = *(const float4*)&kv[j * 64 + d];
                o[d + 0] = fmaf(p, v4.x, o[d + 0]);
                o[d + 1] = fmaf(p, v4.y, o[d + 1]);
                o[d + 2] = fmaf(p, v4.z, o[d + 2]);
                o[d + 3] = fmaf(p, v4.w, o[d + 3]);
            }
        }
    }

    __syncthreads();
#pragma unroll
    for (int d = 0; d < 64; d++) sc[r * SROW + d] = o[d] * invsum;
    __syncthreads();
    for (int rr = r8; rr < W_; rr += 8) {
        const float* src = &sc[rr * SROW + c16 * 4];
        float4 val;
        val.x = src[0]; val.y = src[1]; val.z = src[2]; val.w = src[3];
        *(float4*)&ctx[(size_t)(rowbase + rr) * HID_ + h * HD_ + c16 * 4] = val;
    }
}

// ---------------------------------------------------------------------------
// Launch
// ---------------------------------------------------------------------------
extern "C" void kernel_launch(void* const* d_in, const int* in_sizes, int n_in,
                              void* d_out, int out_size)
{
    const float* hidden = (const float*)d_in[0];
    const float* Wq = (const float*)d_in[1];
    const float* bq = (const float*)d_in[2];
    const float* Wk = (const float*)d_in[3];
    const float* bk = (const float*)d_in[4];
    const float* Wv = (const float*)d_in[5];
    const float* bv = (const float*)d_in[6];
    const float* Wo = (const float*)d_in[7];
    const float* bo = (const float*)d_in[8];
    float* out = (float*)d_out;

    float *qp, *kp, *vp, *cp;
    __nv_bfloat16 *a2, *b2;
    cudaGetSymbolAddress((void**)&qp, g_q);
    cudaGetSymbolAddress((void**)&kp, g_k);
    cudaGetSymbolAddress((void**)&vp, g_v);
    cudaGetSymbolAddress((void**)&cp, g_ctx);
    cudaGetSymbolAddress((void**)&a2, g_A2);
    cudaGetSymbolAddress((void**)&b2, g_B2);
    __nv_bfloat16* b2w[4];
    for (int i = 0; i < 4; i++) b2w[i] = b2 + (size_t)i * HID_ * KPK;

    cudaFuncSetAttribute(swattn_kernel,
                         cudaFuncAttributeMaxDynamicSharedMemorySize, ATT_SMEM);
    cudaFuncSetAttribute(gemm_bf16_kernel,
                         cudaFuncAttributeMaxDynamicSharedMemorySize, GEMM_SMEM);

    // Pack weights (mode 1: hi|hi|lo) and activations (mode 0: hi|lo|hi)
    pack_split3_kernel<<<1024, 256>>>(Wq, b2w[0], 1);
    pack_split3_kernel<<<1024, 256>>>(Wk, b2w[1], 1);
    pack_split3_kernel<<<1024, 256>>>(Wv, b2w[2], 1);
    pack_split3_kernel<<<1024, 256>>>(Wo, b2w[3], 1);
    pack_split3_kernel<<<8192, 256>>>(hidden, a2, 0);

    dim3 ggrid(HID_ / 128, M_ / 128);   // (8, 64)
    gemm_bf16_kernel<<<ggrid, 256, GEMM_SMEM>>>(a2, b2w[0], bq, qp);
    gemm_bf16_kernel<<<ggrid, 256, GEMM_SMEM>>>(a2, b2w[1], bk, kp);
    gemm_bf16_kernel<<<ggrid, 256, GEMM_SMEM>>>(a2, b2w[2], bv, vp);

    rope_kernel<<<(M_ * NH_ * 32) / 256, 256>>>(qp, kp);

    dim3 att_grid(NB_, NH_, B_);
    swattn_kernel<<<att_grid, 128, ATT_SMEM>>>(qp, kp, vp, cp);

    pack_split3_kernel<<<8192, 256>>>(cp, a2, 0);
    gemm_bf16_kernel<<<ggrid, 256, GEMM_SMEM>>>(a2, b2w[3], bo, out);
}